// round 1
// baseline (speedup 1.0000x reference)
#include <cuda_runtime.h>

#define B_  4
#define L_  1024
#define H_  1024
#define NH_ 16
#define HD_ 64
#define M_  (B_*L_)   // 4096

// Scratch (static device globals; no runtime allocation allowed)
__device__ float g_Q  [M_ * H_];        // 16 MB  [B*L, H]
__device__ float g_KVs[M_ * 2 * H_];    // 32 MB  [B*L, 2H]
__device__ float g_KVl[M_ * 2 * H_];    // 32 MB
__device__ float g_mix[M_ * H_];        // 16 MB  mixed attention output

// ---------------------------------------------------------------------------
// Classic 128x128x16 fp32 SIMT GEMM, 256 threads, 8x8 per-thread microtile.
// C[M,N] = A[M,K] @ B[K,N], all row-major, dims divisible by tile sizes.
// ---------------------------------------------------------------------------
__global__ __launch_bounds__(256) void sgemm128(
    const float* __restrict__ A, const float* __restrict__ Bm,
    float* __restrict__ C, int M, int N, int K)
{
    constexpr int BM = 128, BN = 128, BK = 16, TM = 8, TN = 8;
    __shared__ float As[BK][BM];   // transposed A tile
    __shared__ float Bs[BK][BN];

    const int tid = threadIdx.x;
    const float* Ab = A + (size_t)blockIdx.y * BM * K;
    const float* Bb = Bm + (size_t)blockIdx.x * BN;
    float* Cb = C + (size_t)blockIdx.y * BM * N + (size_t)blockIdx.x * BN;

    const int arow = tid >> 2;          // 0..63 (two passes, +64)
    const int acol = (tid & 3) << 2;    // 0,4,8,12
    const int brow = tid >> 5;          // 0..7 (two passes, +8)
    const int bcol = (tid & 31) << 2;   // 0..124
    const int ty = tid >> 4, tx = tid & 15;

    float acc[TM][TN] = {};

    for (int k0 = 0; k0 < K; k0 += BK) {
#pragma unroll
        for (int i = 0; i < 2; i++) {
            float4 v = *reinterpret_cast<const float4*>(
                Ab + (size_t)(arow + i * 64) * K + k0 + acol);
            As[acol + 0][arow + i * 64] = v.x;
            As[acol + 1][arow + i * 64] = v.y;
            As[acol + 2][arow + i * 64] = v.z;
            As[acol + 3][arow + i * 64] = v.w;
        }
#pragma unroll
        for (int i = 0; i < 2; i++) {
            *reinterpret_cast<float4*>(&Bs[brow + i * 8][bcol]) =
                *reinterpret_cast<const float4*>(
                    Bb + (size_t)(k0 + brow + i * 8) * N + bcol);
        }
        __syncthreads();

#pragma unroll
        for (int kk = 0; kk < BK; kk++) {
            float ar[TM], br[TN];
            *reinterpret_cast<float4*>(&ar[0]) = *reinterpret_cast<float4*>(&As[kk][ty * TM]);
            *reinterpret_cast<float4*>(&ar[4]) = *reinterpret_cast<float4*>(&As[kk][ty * TM + 4]);
            *reinterpret_cast<float4*>(&br[0]) = *reinterpret_cast<float4*>(&Bs[kk][tx * TN]);
            *reinterpret_cast<float4*>(&br[4]) = *reinterpret_cast<float4*>(&Bs[kk][tx * TN + 4]);
#pragma unroll
            for (int i = 0; i < TM; i++)
#pragma unroll
                for (int j = 0; j < TN; j++)
                    acc[i][j] += ar[i] * br[j];
        }
        __syncthreads();
    }

#pragma unroll
    for (int i = 0; i < TM; i++)
#pragma unroll
        for (int j = 0; j < TN; j += 4) {
            float4 v = make_float4(acc[i][j], acc[i][j + 1], acc[i][j + 2], acc[i][j + 3]);
            *reinterpret_cast<float4*>(Cb + (size_t)(ty * TM + i) * N + tx * TN + j) = v;
        }
}

// ---------------------------------------------------------------------------
// Fused dual-branch flash attention + mix.
// Block = (q_tile of 64, head, batch), 256 threads.
// Branch 0: short KV with decay bias; branch 1: long KV, no bias.
// Online softmax; output mixed in-register; writes g_mix[B*L, H].
// smem: qs[64][68] (q^T, pre-scaled), kp[64][68] (K^T then P[k][q]), vs[64][64].
// ---------------------------------------------------------------------------
#define ATTN_SMEM ((2 * 64 * 68 + 64 * 64) * 4)   // 51200 bytes

__global__ __launch_bounds__(256) void attn_kernel(
    const float* __restrict__ Q, const float* __restrict__ KVs,
    const float* __restrict__ KVl, float* __restrict__ Out,
    const float* __restrict__ p_mixw, const float* __restrict__ p_decay)
{
    extern __shared__ float sm[];
    float* qs = sm;                 // qs[d*68 + q]
    float* kp = sm + 64 * 68;       // K: kp[d*68 + k] ; P: kp[k*68 + q]
    float* vs = sm + 2 * 64 * 68;   // vs[k*64 + d]

    const int tid = threadIdx.x;
    const int q0 = blockIdx.x * 64;
    const int h  = blockIdx.y;
    const int b  = blockIdx.z;
    const int tq = tid >> 4;        // 0..15 -> queries 4*tq..+3
    const int tx = tid & 15;        // 0..15 -> keys (S-pass) / dims (PV-pass)

    const float alpha  = 1.0f / (1.0f + __expf(-p_mixw[0]));
    const float lambda = 1.0f - p_decay[0];

    // Load Q tile, transposed + pre-scaled by 1/sqrt(hd)
    {
        const float* qbase = Q + ((size_t)(b * L_) + q0) * H_ + h * HD_;
        const int r  = tid >> 2;   // query row 0..63
        const int cg = tid & 3;
#pragma unroll
        for (int it = 0; it < 4; it++) {
            const int d0 = (cg + it * 4) * 4;
            float4 v = *reinterpret_cast<const float4*>(qbase + (size_t)r * H_ + d0);
            qs[(d0 + 0) * 68 + r] = v.x * 0.125f;
            qs[(d0 + 1) * 68 + r] = v.y * 0.125f;
            qs[(d0 + 2) * 68 + r] = v.z * 0.125f;
            qs[(d0 + 3) * 68 + r] = v.w * 0.125f;
        }
    }

    float omix[4][4];

    for (int branch = 0; branch < 2; branch++) {
        const float* KV = (branch == 0) ? KVs : KVl;
        const bool use_bias = (branch == 0);

        float m[4], l[4], o[4][4];
#pragma unroll
        for (int i = 0; i < 4; i++) {
            m[i] = -1e30f; l[i] = 0.0f;
#pragma unroll
            for (int j = 0; j < 4; j++) o[i][j] = 0.0f;
        }

        for (int t = 0; t < L_ / 64; t++) {
            __syncthreads();   // prior PV-pass / Q-load complete

            // Load K (transposed) and V (row-major) tiles
            {
                const float* kb = KV + ((size_t)(b * L_) + t * 64) * (2 * H_) + h * HD_;
                const float* vb = kb + H_;
                const int r  = tid >> 2;
                const int cg = tid & 3;
#pragma unroll
                for (int it = 0; it < 4; it++) {
                    const int d0 = (cg + it * 4) * 4;
                    float4 k4 = *reinterpret_cast<const float4*>(kb + (size_t)r * (2 * H_) + d0);
                    kp[(d0 + 0) * 68 + r] = k4.x;
                    kp[(d0 + 1) * 68 + r] = k4.y;
                    kp[(d0 + 2) * 68 + r] = k4.z;
                    kp[(d0 + 3) * 68 + r] = k4.w;
                    float4 v4 = *reinterpret_cast<const float4*>(vb + (size_t)r * (2 * H_) + d0);
                    *reinterpret_cast<float4*>(&vs[r * 64 + d0]) = v4;
                }
            }
            __syncthreads();

            // S-pass: s[i][j] = q(4tq+i) . k(4tx+j)
            float s[4][4] = {};
#pragma unroll 8
            for (int d = 0; d < 64; d++) {
                float4 qa = *reinterpret_cast<float4*>(&qs[d * 68 + 4 * tq]);
                float4 ka = *reinterpret_cast<float4*>(&kp[d * 68 + 4 * tx]);
                float qv[4] = {qa.x, qa.y, qa.z, qa.w};
                float kv[4] = {ka.x, ka.y, ka.z, ka.w};
#pragma unroll
                for (int i = 0; i < 4; i++)
#pragma unroll
                    for (int j = 0; j < 4; j++)
                        s[i][j] += qv[i] * kv[j];
            }

            if (use_bias) {
#pragma unroll
                for (int i = 0; i < 4; i++) {
                    const float dq = (float)(q0 + 4 * tq + i);
#pragma unroll
                    for (int j = 0; j < 4; j++) {
                        const float dk = (float)(t * 64 + 4 * tx + j);
                        s[i][j] -= fabsf(dq - dk) * lambda;
                    }
                }
            }

            // Online softmax (row groups = 16 consecutive lanes share a query)
            float p[4][4];
#pragma unroll
            for (int i = 0; i < 4; i++) {
                float mt = fmaxf(fmaxf(s[i][0], s[i][1]), fmaxf(s[i][2], s[i][3]));
#pragma unroll
                for (int off = 8; off >= 1; off >>= 1)
                    mt = fmaxf(mt, __shfl_xor_sync(0xffffffffu, mt, off, 32));
                const float mn = fmaxf(m[i], mt);
                const float c  = __expf(m[i] - mn);
                float ls = 0.0f;
#pragma unroll
                for (int j = 0; j < 4; j++) {
                    p[i][j] = __expf(s[i][j] - mn);
                    ls += p[i][j];
                }
#pragma unroll
                for (int off = 8; off >= 1; off >>= 1)
                    ls += __shfl_xor_sync(0xffffffffu, ls, off, 32);
                l[i] = l[i] * c + ls;
                m[i] = mn;
#pragma unroll
                for (int j = 0; j < 4; j++) o[i][j] *= c;
            }
            __syncthreads();   // all threads done reading kp as K

            // Write P transposed: kp[k][q] (float4 along q)
#pragma unroll
            for (int j = 0; j < 4; j++) {
                float4 pv = make_float4(p[0][j], p[1][j], p[2][j], p[3][j]);
                *reinterpret_cast<float4*>(&kp[(4 * tx + j) * 68 + 4 * tq]) = pv;
            }
            __syncthreads();

            // PV-pass: o[i][j] += sum_k P[k][4tq+i] * V[k][4tx+j]
#pragma unroll 8
            for (int k = 0; k < 64; k++) {
                float4 pa = *reinterpret_cast<float4*>(&kp[k * 68 + 4 * tq]);
                float4 va = *reinterpret_cast<float4*>(&vs[k * 64 + 4 * tx]);
                float pv[4] = {pa.x, pa.y, pa.z, pa.w};
                float vv[4] = {va.x, va.y, va.z, va.w};
#pragma unroll
                for (int i = 0; i < 4; i++)
#pragma unroll
                    for (int j = 0; j < 4; j++)
                        o[i][j] += pv[i] * vv[j];
            }
        }

        // Finalize branch and mix
        const float w = (branch == 0) ? alpha : (1.0f - alpha);
#pragma unroll
        for (int i = 0; i < 4; i++) {
            const float inv = 1.0f / l[i];
#pragma unroll
            for (int j = 0; j < 4; j++) {
                const float val = o[i][j] * inv * w;
                if (branch == 0) omix[i][j] = val;
                else             omix[i][j] += val;
            }
        }
    }

    // Store mixed output: Out[b*L + q, h*64 + d]
    float* ob = Out + ((size_t)(b * L_) + q0) * H_ + h * HD_;
#pragma unroll
    for (int i = 0; i < 4; i++) {
        float4 v = make_float4(omix[i][0], omix[i][1], omix[i][2], omix[i][3]);
        *reinterpret_cast<float4*>(ob + (size_t)(4 * tq + i) * H_ + 4 * tx) = v;
    }
}

// ---------------------------------------------------------------------------
extern "C" void kernel_launch(void* const* d_in, const int* in_sizes, int n_in,
                              void* d_out, int out_size)
{
    const float* x     = (const float*)d_in[0];
    const float* Wq    = (const float*)d_in[1];
    const float* Wkvs  = (const float*)d_in[2];
    const float* Wkvl  = (const float*)d_in[3];
    const float* Wo    = (const float*)d_in[4];
    const float* mixw  = (const float*)d_in[5];
    const float* decay = (const float*)d_in[6];
    float* out = (float*)d_out;

    float *pQ, *pKVs, *pKVl, *pmix;
    cudaGetSymbolAddress((void**)&pQ,   g_Q);
    cudaGetSymbolAddress((void**)&pKVs, g_KVs);
    cudaGetSymbolAddress((void**)&pKVl, g_KVl);
    cudaGetSymbolAddress((void**)&pmix, g_mix);

    cudaFuncSetAttribute(attn_kernel,
                         cudaFuncAttributeMaxDynamicSharedMemorySize, ATTN_SMEM);

    dim3 blk(256);
    // Projections
    sgemm128<<<dim3(H_ / 128,     M_ / 128), blk>>>(x, Wq,   pQ,   M_, H_,     H_);
    sgemm128<<<dim3(2 * H_ / 128, M_ / 128), blk>>>(x, Wkvs, pKVs, M_, 2 * H_, H_);
    sgemm128<<<dim3(2 * H_ / 128, M_ / 128), blk>>>(x, Wkvl, pKVl, M_, 2 * H_, H_);
    // Fused dual-branch attention + mix
    attn_kernel<<<dim3(L_ / 64, NH_, B_), blk, ATTN_SMEM>>>(pQ, pKVs, pKVl, pmix,
                                                            mixw, decay);
    // Output projection
    sgemm128<<<dim3(H_ / 128, M_ / 128), blk>>>(pmix, Wo, out, M_, H_, H_);
}

// round 2
// speedup vs baseline: 2.6775x; 2.6775x over previous
#include <cuda_runtime.h>
#include <cstdint>

#define B_  4
#define L_  1024
#define H_  1024
#define NH_ 16
#define HD_ 64
#define M_  (B_*L_)   // 4096

// Scratch (static device globals; no runtime allocation allowed)
__device__ float g_Q  [M_ * H_];        // [B*L, H]
__device__ float g_KVs[M_ * 2 * H_];    // [B*L, 2H]
__device__ float g_KVl[M_ * 2 * H_];
__device__ float g_mix[M_ * H_];

// ---------------------------------------------------------------------------
// helpers
// ---------------------------------------------------------------------------
__device__ __forceinline__ unsigned f2tf(float x) {
    unsigned u;
    asm("cvt.rna.tf32.f32 %0, %1;" : "=r"(u) : "f"(x));
    return u;
}

__device__ __forceinline__ void mma8(float& d0, float& d1, float& d2, float& d3,
                                     unsigned a0, unsigned a1, unsigned a2, unsigned a3,
                                     unsigned b0, unsigned b1) {
    asm volatile(
        "mma.sync.aligned.m16n8k8.row.col.f32.tf32.tf32.f32 "
        "{%0,%1,%2,%3}, {%4,%5,%6,%7}, {%8,%9}, {%0,%1,%2,%3};"
        : "+f"(d0), "+f"(d1), "+f"(d2), "+f"(d3)
        : "r"(a0), "r"(a1), "r"(a2), "r"(a3), "r"(b0), "r"(b1));
}

__device__ __forceinline__ void cp16(void* smem_dst, const void* gmem_src) {
    unsigned s = (unsigned)__cvta_generic_to_shared(smem_dst);
    asm volatile("cp.async.cg.shared.global [%0], [%1], 16;" :: "r"(s), "l"(gmem_src));
}

// ---------------------------------------------------------------------------
// tf32 mma GEMM: C[M,N] = A[M,K] @ B[K,N], row-major, dims % (128,128,32)==0.
// 256 threads, warp grid 2(M)x4(N), warp tile 64x32, m16n8k8, cp.async DB.
// Fragments cvt'd to tf32 at load (smem holds raw fp32).
// ---------------------------------------------------------------------------
#define GA_S 36     // As row stride (words) — %32==4 -> conflict-free A-frag LDS
#define GB_S 136    // Bs row stride (words) — %32==8 -> conflict-free B-frag LDS
#define GEMM_SMEM ((2*128*GA_S + 2*32*GB_S) * 4)   // 71680 B

__global__ __launch_bounds__(256, 2) void gemm_tf32(
    const float* __restrict__ A, const float* __restrict__ Bm,
    float* __restrict__ C, int M, int N, int K)
{
    extern __shared__ float sm[];
    float* As = sm;                   // [2][128][GA_S]
    float* Bs = sm + 2 * 128 * GA_S;  // [2][32][GB_S]

    const int tid  = threadIdx.x;
    const int lane = tid & 31, wid = tid >> 5;
    const int g = lane >> 2, tg = lane & 3;
    const int wm = (wid & 1) * 64, wn = (wid >> 1) * 32;
    const int bm = blockIdx.y * 128, bn = blockIdx.x * 128;

    const int ar = tid >> 3, ac = (tid & 7) * 4;    // A loads: 32 rows/pass x4
    const int br = tid >> 5, bc = (tid & 31) * 4;   // B loads: 8 rows/pass x4

    float acc[4][4][4];
#pragma unroll
    for (int i = 0; i < 4; i++)
#pragma unroll
        for (int j = 0; j < 4; j++)
#pragma unroll
            for (int r = 0; r < 4; r++) acc[i][j][r] = 0.0f;

    const int NT = K / 32;

    // prologue load
    {
        float* Ad = As;
        float* Bd = Bs;
        const float* Ag = A + (size_t)(bm + ar) * K + ac;
#pragma unroll
        for (int p = 0; p < 4; p++)
            cp16(Ad + (ar + p * 32) * GA_S + ac, Ag + (size_t)p * 32 * K);
        const float* Bg = Bm + (size_t)br * N + bn + bc;
#pragma unroll
        for (int p = 0; p < 4; p++)
            cp16(Bd + (br + p * 8) * GB_S + bc, Bg + (size_t)p * 8 * N);
        asm volatile("cp.async.commit_group;");
    }

    for (int t = 0; t < NT; t++) {
        asm volatile("cp.async.wait_group 0;");
        __syncthreads();

        if (t + 1 < NT) {
            const int k0 = (t + 1) * 32;
            float* Ad = As + ((t + 1) & 1) * 128 * GA_S;
            float* Bd = Bs + ((t + 1) & 1) * 32 * GB_S;
            const float* Ag = A + (size_t)(bm + ar) * K + k0 + ac;
#pragma unroll
            for (int p = 0; p < 4; p++)
                cp16(Ad + (ar + p * 32) * GA_S + ac, Ag + (size_t)p * 32 * K);
            const float* Bg = Bm + (size_t)(k0 + br) * N + bn + bc;
#pragma unroll
            for (int p = 0; p < 4; p++)
                cp16(Bd + (br + p * 8) * GB_S + bc, Bg + (size_t)p * 8 * N);
            asm volatile("cp.async.commit_group;");
        }

        const float* Ad = As + (t & 1) * 128 * GA_S;
        const float* Bd = Bs + (t & 1) * 32 * GB_S;
#pragma unroll
        for (int ks = 0; ks < 4; ks++) {
            const int k0 = ks * 8;
            unsigned af[4][4], bf[4][2];
#pragma unroll
            for (int im = 0; im < 4; im++) {
                const float* p = Ad + (wm + im * 16 + g) * GA_S + k0;
                af[im][0] = f2tf(p[tg]);
                af[im][1] = f2tf(p[8 * GA_S + tg]);
                af[im][2] = f2tf(p[tg + 4]);
                af[im][3] = f2tf(p[8 * GA_S + tg + 4]);
            }
#pragma unroll
            for (int jn = 0; jn < 4; jn++) {
                const float* p = Bd + (k0 + tg) * GB_S + wn + jn * 8 + g;
                bf[jn][0] = f2tf(p[0]);
                bf[jn][1] = f2tf(p[4 * GB_S]);
            }
#pragma unroll
            for (int im = 0; im < 4; im++)
#pragma unroll
                for (int jn = 0; jn < 4; jn++)
                    mma8(acc[im][jn][0], acc[im][jn][1], acc[im][jn][2], acc[im][jn][3],
                         af[im][0], af[im][1], af[im][2], af[im][3],
                         bf[jn][0], bf[jn][1]);
        }
        __syncthreads();
    }

    // epilogue
#pragma unroll
    for (int im = 0; im < 4; im++)
#pragma unroll
        for (int jn = 0; jn < 4; jn++) {
            const int row = bm + wm + im * 16 + g;
            const int col = bn + wn + jn * 8 + 2 * tg;
            *(float2*)&C[(size_t)row * N + col] =
                make_float2(acc[im][jn][0], acc[im][jn][1]);
            *(float2*)&C[(size_t)(row + 8) * N + col] =
                make_float2(acc[im][jn][2], acc[im][jn][3]);
        }
}

// ---------------------------------------------------------------------------
// Dual-branch flash attention with tf32 mma.
// Block: 128 queries x (head, batch), 256 threads = 8 warps, 16 q-rows/warp.
// smem holds tf32 bit patterns (converted at store time).
// ---------------------------------------------------------------------------
#define SQ 68   // Qs/Ps row stride (words), %32==4
#define SK 72   // Ks/Vs row stride (words), %32==8
#define ATTN_SMEM ((2*128*SQ + 2*64*SK) * 4)   // 106496 B

__global__ __launch_bounds__(256, 1) void attn_mma(
    const float* __restrict__ Q, const float* __restrict__ KVs,
    const float* __restrict__ KVl, float* __restrict__ Out,
    const float* __restrict__ p_mixw, const float* __restrict__ p_decay)
{
    extern __shared__ float sm[];
    float* Qs = sm;                  // [128][SQ]   Q (tf32 bits, pre-scaled)
    float* Ps = sm + 128 * SQ;       // [128][SQ]   P (tf32 bits)
    float* Ks = sm + 2 * 128 * SQ;   // [64][SK]    K^T: [d][key]
    float* Vs = Ks + 64 * SK;        // [64][SK]    V:   [key][d]

    const int tid = threadIdx.x, lane = tid & 31, wid = tid >> 5;
    const int g = lane >> 2, tg = lane & 3;
    const int q0 = blockIdx.x * 128;
    const int h = blockIdx.y, b = blockIdx.z;
    const int mw = wid * 16;

    const float alpha  = 1.0f / (1.0f + __expf(-p_mixw[0]));
    const float lambda = 1.0f - p_decay[0];
    const float wmix[2] = {alpha, 1.0f - alpha};

    // Load Q tile (pre-scaled by 1/sqrt(64), converted to tf32)
    {
        const int r = tid >> 1, half = tid & 1;
        const float* qb = Q + ((size_t)(b * L_ + q0 + r)) * H_ + h * HD_ + half * 32;
        float* qd = Qs + r * SQ + half * 32;
#pragma unroll
        for (int j = 0; j < 8; j++) {
            float4 v = *(const float4*)(qb + j * 4);
            qd[j * 4 + 0] = __uint_as_float(f2tf(v.x * 0.125f));
            qd[j * 4 + 1] = __uint_as_float(f2tf(v.y * 0.125f));
            qd[j * 4 + 2] = __uint_as_float(f2tf(v.z * 0.125f));
            qd[j * 4 + 3] = __uint_as_float(f2tf(v.w * 0.125f));
        }
    }

    for (int branch = 0; branch < 2; branch++) {
        const float* KV = branch ? KVl : KVs;
        float mrow[2] = {-1e30f, -1e30f};
        float lrow[2] = {0.0f, 0.0f};
        float o[8][4];
#pragma unroll
        for (int jn = 0; jn < 8; jn++)
#pragma unroll
            for (int r = 0; r < 4; r++) o[jn][r] = 0.0f;

        for (int t = 0; t < L_ / 64; t++) {
            __syncthreads();   // prior tile's PV (all warps) complete
            // Load K (transposed) + V tiles, cvt to tf32 at store
            {
                const int r = tid >> 2, cg = tid & 3;
                const float* kb = KV + ((size_t)(b * L_ + t * 64 + r)) * (2 * H_) + h * HD_;
                const float* vb = kb + H_;
#pragma unroll
                for (int it = 0; it < 4; it++) {
                    const int d0 = (cg + it * 4) * 4;
                    float4 k4 = *(const float4*)(kb + d0);
                    Ks[(d0 + 0) * SK + r] = __uint_as_float(f2tf(k4.x));
                    Ks[(d0 + 1) * SK + r] = __uint_as_float(f2tf(k4.y));
                    Ks[(d0 + 2) * SK + r] = __uint_as_float(f2tf(k4.z));
                    Ks[(d0 + 3) * SK + r] = __uint_as_float(f2tf(k4.w));
                    float4 v4 = *(const float4*)(vb + d0);
                    Vs[r * SK + d0 + 0] = __uint_as_float(f2tf(v4.x));
                    Vs[r * SK + d0 + 1] = __uint_as_float(f2tf(v4.y));
                    Vs[r * SK + d0 + 2] = __uint_as_float(f2tf(v4.z));
                    Vs[r * SK + d0 + 3] = __uint_as_float(f2tf(v4.w));
                }
            }
            __syncthreads();

            // ---- S = Q K^T (this warp: 16 rows x 64 keys) ----
            float s[8][4];
#pragma unroll
            for (int jn = 0; jn < 8; jn++)
#pragma unroll
                for (int r = 0; r < 4; r++) s[jn][r] = 0.0f;

#pragma unroll
            for (int ks = 0; ks < 8; ks++) {
                const int k0 = ks * 8;
                const float* qp = Qs + (mw + g) * SQ + k0;
                unsigned a0 = __float_as_uint(qp[tg]);
                unsigned a1 = __float_as_uint(qp[8 * SQ + tg]);
                unsigned a2 = __float_as_uint(qp[tg + 4]);
                unsigned a3 = __float_as_uint(qp[8 * SQ + tg + 4]);
#pragma unroll
                for (int jn = 0; jn < 8; jn++) {
                    const float* kpp = Ks + (k0 + tg) * SK + jn * 8 + g;
                    unsigned b0 = __float_as_uint(kpp[0]);
                    unsigned b1 = __float_as_uint(kpp[4 * SK]);
                    mma8(s[jn][0], s[jn][1], s[jn][2], s[jn][3], a0, a1, a2, a3, b0, b1);
                }
            }

            if (branch == 0) {
                const float r0 = (float)(q0 + mw + g), r1 = r0 + 8.0f;
#pragma unroll
                for (int jn = 0; jn < 8; jn++) {
                    const float c0 = (float)(t * 64 + jn * 8 + 2 * tg), c1 = c0 + 1.0f;
                    s[jn][0] -= fabsf(r0 - c0) * lambda;
                    s[jn][1] -= fabsf(r0 - c1) * lambda;
                    s[jn][2] -= fabsf(r1 - c0) * lambda;
                    s[jn][3] -= fabsf(r1 - c1) * lambda;
                }
            }

            // ---- online softmax (rows mw+g and mw+g+8; quad = full row) ----
            float mt0 = -1e30f, mt1 = -1e30f;
#pragma unroll
            for (int jn = 0; jn < 8; jn++) {
                mt0 = fmaxf(mt0, fmaxf(s[jn][0], s[jn][1]));
                mt1 = fmaxf(mt1, fmaxf(s[jn][2], s[jn][3]));
            }
            mt0 = fmaxf(mt0, __shfl_xor_sync(0xffffffffu, mt0, 1));
            mt0 = fmaxf(mt0, __shfl_xor_sync(0xffffffffu, mt0, 2));
            mt1 = fmaxf(mt1, __shfl_xor_sync(0xffffffffu, mt1, 1));
            mt1 = fmaxf(mt1, __shfl_xor_sync(0xffffffffu, mt1, 2));
            const float mn0 = fmaxf(mrow[0], mt0), mn1 = fmaxf(mrow[1], mt1);
            const float c0 = __expf(mrow[0] - mn0), c1 = __expf(mrow[1] - mn1);
            mrow[0] = mn0; mrow[1] = mn1;

            float ls0 = 0.0f, ls1 = 0.0f;
            float* pd = Ps + (mw + g) * SQ;
#pragma unroll
            for (int jn = 0; jn < 8; jn++) {
                const int col = jn * 8 + 2 * tg;
                const float p0 = __expf(s[jn][0] - mn0);
                const float p1 = __expf(s[jn][1] - mn0);
                const float p2 = __expf(s[jn][2] - mn1);
                const float p3 = __expf(s[jn][3] - mn1);
                ls0 += p0 + p1; ls1 += p2 + p3;
                pd[col]              = __uint_as_float(f2tf(p0));
                pd[col + 1]          = __uint_as_float(f2tf(p1));
                pd[8 * SQ + col]     = __uint_as_float(f2tf(p2));
                pd[8 * SQ + col + 1] = __uint_as_float(f2tf(p3));
            }
            ls0 += __shfl_xor_sync(0xffffffffu, ls0, 1);
            ls0 += __shfl_xor_sync(0xffffffffu, ls0, 2);
            ls1 += __shfl_xor_sync(0xffffffffu, ls1, 1);
            ls1 += __shfl_xor_sync(0xffffffffu, ls1, 2);
            lrow[0] = lrow[0] * c0 + ls0;
            lrow[1] = lrow[1] * c1 + ls1;

#pragma unroll
            for (int jn = 0; jn < 8; jn++) {
                o[jn][0] *= c0; o[jn][1] *= c0;
                o[jn][2] *= c1; o[jn][3] *= c1;
            }
            __syncwarp();   // P visible to whole warp (rows are warp-private)

            // ---- O += P V ----
#pragma unroll
            for (int ks = 0; ks < 8; ks++) {
                const int k0 = ks * 8;
                const float* pp = Ps + (mw + g) * SQ + k0;
                unsigned a0 = __float_as_uint(pp[tg]);
                unsigned a1 = __float_as_uint(pp[8 * SQ + tg]);
                unsigned a2 = __float_as_uint(pp[tg + 4]);
                unsigned a3 = __float_as_uint(pp[8 * SQ + tg + 4]);
#pragma unroll
                for (int jn = 0; jn < 8; jn++) {
                    const float* vp = Vs + (k0 + tg) * SK + jn * 8 + g;
                    unsigned b0 = __float_as_uint(vp[0]);
                    unsigned b1 = __float_as_uint(vp[4 * SK]);
                    mma8(o[jn][0], o[jn][1], o[jn][2], o[jn][3], a0, a1, a2, a3, b0, b1);
                }
            }
        }

        // ---- branch epilogue: scale by weight/l, mix into Out ----
        const float w  = wmix[branch];
        const float i0 = w / lrow[0], i1 = w / lrow[1];
        float* ob = Out + ((size_t)(b * L_ + q0 + mw + g)) * H_ + h * HD_;
        if (branch == 0) {
#pragma unroll
            for (int jn = 0; jn < 8; jn++) {
                const int col = jn * 8 + 2 * tg;
                *(float2*)(ob + col)          = make_float2(o[jn][0] * i0, o[jn][1] * i0);
                *(float2*)(ob + 8 * H_ + col) = make_float2(o[jn][2] * i1, o[jn][3] * i1);
            }
        } else {
#pragma unroll
            for (int jn = 0; jn < 8; jn++) {
                const int col = jn * 8 + 2 * tg;
                float2 u0 = *(float2*)(ob + col);
                float2 u1 = *(float2*)(ob + 8 * H_ + col);
                *(float2*)(ob + col) =
                    make_float2(u0.x + o[jn][0] * i0, u0.y + o[jn][1] * i0);
                *(float2*)(ob + 8 * H_ + col) =
                    make_float2(u1.x + o[jn][2] * i1, u1.y + o[jn][3] * i1);
            }
        }
    }
}

// ---------------------------------------------------------------------------
extern "C" void kernel_launch(void* const* d_in, const int* in_sizes, int n_in,
                              void* d_out, int out_size)
{
    const float* x     = (const float*)d_in[0];
    const float* Wq    = (const float*)d_in[1];
    const float* Wkvs  = (const float*)d_in[2];
    const float* Wkvl  = (const float*)d_in[3];
    const float* Wo    = (const float*)d_in[4];
    const float* mixw  = (const float*)d_in[5];
    const float* decay = (const float*)d_in[6];
    float* out = (float*)d_out;

    float *pQ, *pKVs, *pKVl, *pmix;
    cudaGetSymbolAddress((void**)&pQ,   g_Q);
    cudaGetSymbolAddress((void**)&pKVs, g_KVs);
    cudaGetSymbolAddress((void**)&pKVl, g_KVl);
    cudaGetSymbolAddress((void**)&pmix, g_mix);

    cudaFuncSetAttribute(gemm_tf32,
                         cudaFuncAttributeMaxDynamicSharedMemorySize, GEMM_SMEM);
    cudaFuncSetAttribute(attn_mma,
                         cudaFuncAttributeMaxDynamicSharedMemorySize, ATTN_SMEM);

    dim3 blk(256);
    // Projections
    gemm_tf32<<<dim3(H_ / 128,     M_ / 128), blk, GEMM_SMEM>>>(x, Wq,   pQ,   M_, H_,     H_);
    gemm_tf32<<<dim3(2 * H_ / 128, M_ / 128), blk, GEMM_SMEM>>>(x, Wkvs, pKVs, M_, 2 * H_, H_);
    gemm_tf32<<<dim3(2 * H_ / 128, M_ / 128), blk, GEMM_SMEM>>>(x, Wkvl, pKVl, M_, 2 * H_, H_);
    // Fused dual-branch attention + mix
    attn_mma<<<dim3(L_ / 128, NH_, B_), blk, ATTN_SMEM>>>(pQ, pKVs, pKVl, pmix,
                                                          mixw, decay);
    // Output projection
    gemm_tf32<<<dim3(H_ / 128, M_ / 128), blk, GEMM_SMEM>>>(pmix, Wo, out, M_, H_, H_);
}